// round 7
// baseline (speedup 1.0000x reference)
#include <cuda_runtime.h>
#include <cuda_fp16.h>
#include <mma.h>
#include <math.h>

using namespace nvcuda;

#define NN 40000
#define NE 640000
#define DD 64
#define KK2 25

// ---------------- scratch (device globals) ----------------------------------
__device__ __half g_Yh[(size_t)NN * KK2 * DD];  // 128 MB  Y[n][k][o] fp16
__device__ __half g_Xh[(size_t)NN * DD];        // fp16 MMA input (x, then H)
__device__ __half g_Wh[KK2 * DD * DD];          // fp16 W of current layer
__device__ float  g_H[(size_t)NN * DD];         // fp32 layer-1 output
__device__ int    g_SRC[NE];
__device__ int    g_DST[NE];
__device__ int    g_OFF[NN + 1];                // CSR row offsets (by dst)
__device__ int    g_CUR[NN];                    // histogram / scatter cursor
__device__ int    g_ES[NE];                     // src*25+base, dst-sorted
__device__ float4 g_EW[NE];                     // B0..B3, dst-sorted

// ---------------- 0a) normalize edge_index (int32 OR int64) -----------------
__global__ void convert_idx_kernel(const int* __restrict__ ei32) {
    bool is64 = true;
    for (int i = 0; i < 8; i++) is64 &= (__ldg(ei32 + 2 * i + 1) == 0);
    int e = blockIdx.x * blockDim.x + threadIdx.x;
    if (e >= NE) return;
    int s, d;
    if (is64) { s = __ldg(ei32 + 2 * e); d = __ldg(ei32 + 2 * (NE + e)); }
    else      { s = __ldg(ei32 + e);     d = __ldg(ei32 + NE + e); }
    g_SRC[e] = min(max(s, 0), NN - 1);
    g_DST[e] = min(max(d, 0), NN - 1);
}

// ---------------- 0b) zero histogram ----------------------------------------
__global__ void zero_cnt_kernel() {
    int n = blockIdx.x * blockDim.x + threadIdx.x;
    if (n < NN) g_CUR[n] = 0;
}

// ---------------- 0c) histogram of dst --------------------------------------
__global__ void hist_kernel() {
    int e = blockIdx.x * blockDim.x + threadIdx.x;
    if (e < NE) atomicAdd(&g_CUR[g_DST[e]], 1);
}

// ---------------- 0d) exclusive scan (1 block) + re-zero cursor -------------
__global__ void scan_kernel() {
    __shared__ int part[1024];
    const int t = threadIdx.x;
    const int CH = (NN + 1023) / 1024;   // 40
    int base = t * CH, s = 0;
    for (int i = 0; i < CH; i++) { int idx = base + i; if (idx < NN) s += g_CUR[idx]; }
    part[t] = s; __syncthreads();
    for (int d = 1; d < 1024; d <<= 1) {
        int v = (t >= d) ? part[t - d] : 0;
        __syncthreads();
        part[t] += v;
        __syncthreads();
    }
    int run = (t > 0) ? part[t - 1] : 0;
    for (int i = 0; i < CH; i++) {
        int idx = base + i;
        if (idx < NN) { int c = g_CUR[idx]; g_OFF[idx] = run; run += c; g_CUR[idx] = 0; }
    }
    if (t == 0) g_OFF[NN] = part[1023];
}

// ---------------- 0e) scatter edges into CSR order, precompute basis --------
__global__ void scatter_kernel(const float* __restrict__ attr) {
    int e = blockIdx.x * blockDim.x + threadIdx.x;
    if (e >= NE) return;
    int src = g_SRC[e], dst = g_DST[e];
    float a0 = __ldg(attr + 2 * e), a1 = __ldg(attr + 2 * e + 1);
    float v0 = a0 * 4.0f, v1 = a1 * 4.0f;
    float b0f = fminf(fmaxf(floorf(v0), 0.0f), 3.0f);
    float b1f = fminf(fmaxf(floorf(v1), 0.0f), 3.0f);
    float f0 = v0 - b0f, f1 = v1 - b1f;
    int base = (int)b0f * 5 + (int)b1f;
    float g0 = 1.0f - f0, g1 = 1.0f - f1;
    int pos = g_OFF[dst] + atomicAdd(&g_CUR[dst], 1);
    g_ES[pos] = src * KK2 + base;
    g_EW[pos] = make_float4(g0 * g1, g0 * f1, f0 * g1, f0 * f1);
}

// ---------------- 0f) fp32 -> fp16 converters -------------------------------
__global__ void convert_x_kernel(const float* __restrict__ X) {
    int i = blockIdx.x * blockDim.x + threadIdx.x;   // over half2
    if (i < NN * DD / 2) {
        float2 v = ((const float2*)X)[i];
        ((__half2*)g_Xh)[i] = __float22half2_rn(v);
    }
}
__global__ void convert_w_kernel(const float* __restrict__ W) {
    int i = blockIdx.x * blockDim.x + threadIdx.x;   // over half2
    if (i < KK2 * DD * DD / 2) {
        float2 v = ((const float2*)W)[i];
        ((__half2*)g_Wh)[i] = __float22half2_rn(v);
    }
}

// ---------------- 1) tensor-core GEMM: one (node-tile, k) per block ----------
// grid = (313, 25), block = 256 (8 warps). warp w computes rows w*16..w*16+15.
// X (5 MB) and W (160 KB fp16) stay L2-resident across blockIdx.y.
#define GTN 128
#define MMA_SMEM (GTN * DD * 2 + DD * DD * 2 + 8 * 16 * DD * 4)  // 16K+8K+32K

__global__ __launch_bounds__(256) void mma_gemm_kernel() {
    extern __shared__ char smraw[];
    __half* xs  = (__half*)smraw;                    // [128][64]
    __half* wsh = (__half*)(smraw + GTN * DD * 2);   // [64][64] (i-major)
    float*  st  = (float*)(smraw + GTN * DD * 2 + DD * DD * 2); // [8][16*64]

    const int t  = threadIdx.x;
    const int w  = t >> 5, lane = t & 31;
    const int n0 = blockIdx.x * GTN;
    const int k  = blockIdx.y;

    // load X tile (zero-fill OOB rows), uint4 = 8 halves
    for (int idx = t; idx < GTN * 8; idx += 256) {
        int n = idx >> 3, u = idx & 7;
        uint4 v = make_uint4(0, 0, 0, 0);
        if (n0 + n < NN) v = ((const uint4*)(g_Xh + (size_t)(n0 + n) * DD))[u];
        ((uint4*)(xs + n * DD))[u] = v;
    }
    // load W[k] tile
    for (int idx = t; idx < DD * 8; idx += 256)
        ((uint4*)wsh)[idx] = ((const uint4*)(g_Wh + k * DD * DD))[idx];
    __syncthreads();

    wmma::fragment<wmma::accumulator, 16, 16, 16, float> acc[4];
    for (int c = 0; c < 4; c++) wmma::fill_fragment(acc[c], 0.0f);

    for (int kk = 0; kk < 4; kk++) {
        wmma::fragment<wmma::matrix_a, 16, 16, 16, __half, wmma::row_major> af;
        wmma::load_matrix_sync(af, xs + (w * 16) * DD + kk * 16, DD);
        for (int c = 0; c < 4; c++) {
            wmma::fragment<wmma::matrix_b, 16, 16, 16, __half, wmma::row_major> bf;
            wmma::load_matrix_sync(bf, wsh + (kk * 16) * DD + c * 16, DD);
            wmma::mma_sync(acc[c], af, bf, acc[c]);
        }
    }

    // stage fp32 in per-warp smem, convert to fp16, write Y row-by-row
    float* stw = st + w * 16 * DD;
    for (int c = 0; c < 4; c++)
        wmma::store_matrix_sync(stw + c * 16, acc[c], DD, wmma::mem_row_major);
    __syncwarp();
    for (int r = 0; r < 16; r++) {
        int gn = n0 + w * 16 + r;
        if (gn < NN) {
            float2 v = *(const float2*)(stw + r * DD + lane * 2);
            *(__half2*)(g_Yh + ((size_t)gn * KK2 + k) * DD + lane * 2) =
                __float22half2_rn(v);
        }
    }
}

// ---------------- 2) fused aggregation + root + bias (+relu) ----------------
// warp per dst node; CSR in-edges; no atomics. Also emits fp16 copy for the
// next layer's MMA when relu!=0 (i.e., layer 1).
__global__ __launch_bounds__(256) void agg_finalize_kernel(
        const float* __restrict__ Xf, const float* __restrict__ root,
        const float* __restrict__ bias, float* __restrict__ outF, int relu) {
    __shared__ float rs[DD * DD];   // root [i][o]
    __shared__ float xsh[8 * DD];   // this block's 8 node rows
    const int t = threadIdx.x;
    const int n0 = blockIdx.x * 8;

    for (int idx = t; idx < DD * DD / 4; idx += 256)
        ((float4*)rs)[idx] = ((const float4*)root)[idx];
    for (int idx = t; idx < 8 * DD / 4; idx += 256)
        ((float4*)xsh)[idx] = ((const float4*)(Xf + (size_t)n0 * DD))[idx];
    __syncthreads();

    const int w = t >> 5, lane = t & 31;
    const int n = n0 + w;
    const int beg = g_OFF[n], end = g_OFF[n + 1];

    float m0 = -INFINITY, m1 = -INFINITY;
    for (int i = beg; i < end; i++) {
        int sb = __ldg(g_ES + i);
        float4 B = __ldg(g_EW + i);
        const __half2* yb = (const __half2*)(g_Yh + (size_t)sb * DD);
        float2 y0 = __half22float2(__ldg(yb + lane));
        float2 y1 = __half22float2(__ldg(yb + 32 + lane));
        float2 y2 = __half22float2(__ldg(yb + 160 + lane));   // +5 rows
        float2 y3 = __half22float2(__ldg(yb + 192 + lane));   // +6 rows
        float s0 = B.x * y0.x + B.y * y1.x + B.z * y2.x + B.w * y3.x;
        float s1 = B.x * y0.y + B.y * y1.y + B.z * y2.y + B.w * y3.y;
        m0 = fmaxf(m0, s0);
        m1 = fmaxf(m1, s1);
    }
    if (!isfinite(m0)) m0 = 0.0f;
    if (!isfinite(m1)) m1 = 0.0f;

    float a0 = m0 + __ldg(bias + lane * 2);
    float a1 = m1 + __ldg(bias + lane * 2 + 1);
    #pragma unroll 8
    for (int i = 0; i < DD; i++) {
        float xi = xsh[w * DD + i];
        float2 rv = *(const float2*)(rs + i * DD + lane * 2);
        a0 = fmaf(xi, rv.x, a0);
        a1 = fmaf(xi, rv.y, a1);
    }
    if (relu) { a0 = fmaxf(a0, 0.0f); a1 = fmaxf(a1, 0.0f); }

    *(float2*)(outF + (size_t)n * DD + lane * 2) = make_float2(a0, a1);
    if (relu)   // layer 1: also produce fp16 input for layer-2 MMA
        *(__half2*)(g_Xh + (size_t)n * DD + lane * 2) =
            __float22half2_rn(make_float2(a0, a1));
}

// ---------------- host launch ------------------------------------------------
extern "C" void kernel_launch(void* const* d_in, const int* in_sizes, int n_in,
                              void* d_out, int out_size) {
    const float* x     = (const float*)d_in[0];
    const int*   ei32  = (const int*)d_in[1];
    const float* attr  = (const float*)d_in[2];
    const float* W1    = (const float*)d_in[3];
    const float* root1 = (const float*)d_in[4];
    const float* bias1 = (const float*)d_in[5];
    const float* W2    = (const float*)d_in[6];
    const float* root2 = (const float*)d_in[7];
    const float* bias2 = (const float*)d_in[8];
    float*       out   = (float*)d_out;

    cudaFuncSetAttribute(mma_gemm_kernel,
                         cudaFuncAttributeMaxDynamicSharedMemorySize, MMA_SMEM);

    float* H = nullptr;
    cudaGetSymbolAddress((void**)&H, g_H);

    const int eb   = (NE + 255) / 256;           // 2500
    const int nb   = (NN + 255) / 256;           // 157
    dim3 mmag((NN + GTN - 1) / GTN, KK2);        // (313, 25)
    const int aggb = NN / 8;                     // 5000
    const int cxb  = (NN * DD / 2 + 255) / 256;  // 5000
    const int cwb  = (KK2 * DD * DD / 2 + 255) / 256;

    // ---- one-time graph preprocessing ----
    convert_idx_kernel<<<eb, 256>>>(ei32);
    zero_cnt_kernel<<<nb, 256>>>();
    hist_kernel<<<eb, 256>>>();
    scan_kernel<<<1, 1024>>>();
    scatter_kernel<<<eb, 256>>>(attr);
    convert_x_kernel<<<cxb, 256>>>(x);

    // ---- layer 1 ----
    convert_w_kernel<<<cwb, 256>>>(W1);
    mma_gemm_kernel<<<mmag, 256, MMA_SMEM>>>();
    agg_finalize_kernel<<<aggb, 256>>>(x, root1, bias1, H, 1);

    // ---- layer 2 ----
    convert_w_kernel<<<cwb, 256>>>(W2);
    mma_gemm_kernel<<<mmag, 256, MMA_SMEM>>>();
    agg_finalize_kernel<<<aggb, 256>>>(H, root2, bias2, out, 0);
}